// round 17
// baseline (speedup 1.0000x reference)
#include <cuda_runtime.h>
#include <cuda_bf16.h>
#include <math.h>
#include <stdint.h>

#define N 8192
#define FIN 256
#define FOUT 64
#define NSPLIT 8    // j-splits per i-tile
#define NTILE 128   // i-rows per CTA
#define JSTEP 32    // j per pipeline step
#define NST 32      // steps per CTA (1024 j per split)
#define PIPE 4      // per-warp ring depth
#define WSTR 36     // padded row stride (ints) -> conflict-free LDS
#define WBUF (16 * WSTR)

// ---------------- device scratch ----------------
__device__ uint4    g_Bfrag[512 * 2 * 4 * 32];  // tf32 B fragments, 2 MB
__device__ float    g_E1[N];
__device__ float    g_E2[N];
__device__ float    g_fsrc[N];
__device__ unsigned g_gmax_enc;
__device__ float    g_Dpart[NSPLIT][(size_t)N * FOUT];
__device__ float    g_lpart[NSPLIT][N];

// ---------------- helpers ----------------
#define CP_ASYNC16(saddr, gptr) \
    asm volatile("cp.async.cg.shared.global [%0], [%1], 16;" ::"r"(saddr), "l"(gptr))
#define CP_COMMIT() asm volatile("cp.async.commit_group;")
#define CP_WAIT(n)  asm volatile("cp.async.wait_group %0;" ::"n"(n))
#define MUL_F32X2(d, a, b) \
    asm("mul.rn.f32x2 %0, %1, %2;" : "=l"(d) : "l"(a), "l"(b))

__device__ __forceinline__ uint32_t f2tf32(float x) {
    uint32_t r;
    asm("cvt.rna.tf32.f32 %0, %1;" : "=r"(r) : "f"(x));
    return r;
}
__device__ __forceinline__ void mma_tf32(float* d, uint32_t a0, uint32_t a1,
                                         uint32_t a2, uint32_t a3, uint32_t b0,
                                         uint32_t b1) {
    asm volatile(
        "mma.sync.aligned.m16n8k8.row.col.f32.tf32.tf32.f32 "
        "{%0,%1,%2,%3}, {%4,%5,%6,%7}, {%8,%9}, {%0,%1,%2,%3};"
        : "+f"(d[0]), "+f"(d[1]), "+f"(d[2]), "+f"(d[3])
        : "r"(a0), "r"(a1), "r"(a2), "r"(a3), "r"(b0), "r"(b1));
}
__device__ __forceinline__ unsigned enc_f(float x) {
    unsigned b = __float_as_uint(x);
    return (b & 0x80000000u) ? ~b : (b | 0x80000000u);
}
__device__ __forceinline__ float dec_f(unsigned k) {
    return __uint_as_float((k & 0x80000000u) ? (k & 0x7fffffffu) : ~k);
}

// ---------------------------------------------------------------------------
// Kernel A (fused): per block of 16 rows,
//   1) Wh tile = h @ W (k-outer/r-inner) -> smem only (g_Wh eliminated)
//   2) f_src/f_dst dots, E1/E2, block max(f_dst) -> one atomic
//   3) tf32 B fragments for this jblock (8 warps = 8 fragment sets)
// ---------------------------------------------------------------------------
__global__ __launch_bounds__(256, 4) void wh_fused_kernel(
    const float* __restrict__ h, const float* __restrict__ W,
    const float* __restrict__ a) {
    __shared__ float Ws[128][FOUT];
    __shared__ float Wt[16][65];
    __shared__ float sdmax[16];

    const int tid = threadIdx.x;
    const int f = tid & 63;
    const int g = tid >> 6;
    const int row0b = blockIdx.x * 16;
    const int row0 = row0b + g * 4;
    float acc0 = 0.f, acc1 = 0.f, acc2 = 0.f, acc3 = 0.f;
    for (int t = 0; t < 2; t++) {
        __syncthreads();
        for (int idx = tid; idx < 128 * FOUT; idx += 256)
            (&Ws[0][0])[idx] = W[t * 128 * FOUT + idx];
        __syncthreads();
        const float4* h0 = (const float4*)(h + (size_t)(row0 + 0) * FIN + t * 128);
        const float4* h1 = (const float4*)(h + (size_t)(row0 + 1) * FIN + t * 128);
        const float4* h2 = (const float4*)(h + (size_t)(row0 + 2) * FIN + t * 128);
        const float4* h3 = (const float4*)(h + (size_t)(row0 + 3) * FIN + t * 128);
#pragma unroll 8
        for (int k4 = 0; k4 < 32; k4++) {
            const float4 v0 = h0[k4], v1 = h1[k4], v2 = h2[k4], v3 = h3[k4];
            const float w0 = Ws[k4 * 4 + 0][f];
            const float w1 = Ws[k4 * 4 + 1][f];
            const float w2 = Ws[k4 * 4 + 2][f];
            const float w3 = Ws[k4 * 4 + 3][f];
            acc0 += v0.x * w0 + v0.y * w1 + v0.z * w2 + v0.w * w3;
            acc1 += v1.x * w0 + v1.y * w1 + v1.z * w2 + v1.w * w3;
            acc2 += v2.x * w0 + v2.y * w1 + v2.z * w2 + v2.w * w3;
            acc3 += v3.x * w0 + v3.y * w1 + v3.z * w2 + v3.w * w3;
        }
    }
    Wt[g * 4 + 0][f] = acc0;
    Wt[g * 4 + 1][f] = acc1;
    Wt[g * 4 + 2][f] = acc2;
    Wt[g * 4 + 3][f] = acc3;
    __syncthreads();

    // ---- fvec: row r = tid>>4, sub k = tid&15 covers f = 4k..4k+3 ----
    {
        const int r = tid >> 4, k = tid & 15;
        float s = 0.f, d = 0.f;
#pragma unroll
        for (int q = 0; q < 4; q++) {
            const float v = Wt[r][k * 4 + q];
            s += v * a[k * 4 + q];
            d += v * a[64 + k * 4 + q];
        }
#pragma unroll
        for (int off = 8; off > 0; off >>= 1) {
            s += __shfl_down_sync(0xffffffffu, s, off);
            d += __shfl_down_sync(0xffffffffu, d, off);
        }
        if (k == 0) {
            const int rg = row0b + r;
            g_fsrc[rg] = s;
            g_E1[rg] = __expf(d);
            g_E2[rg] = __expf(0.2f * d);
            sdmax[r] = d;
        }
    }
    __syncthreads();
    if (tid == 0) {
        float m = sdmax[0];
#pragma unroll
        for (int r = 1; r < 16; r++) m = fmaxf(m, sdmax[r]);
        atomicMax(&g_gmax_enc, enc_f(m));
    }

    // ---- bfrag: warp w -> (kh = w>>2, ntp = w&3); lane -> (g2, tc) ----
    {
        const int w = tid >> 5, lane = tid & 31;
        const int kh = w >> 2, ntp = w & 3;
        const int g2 = lane >> 2, tc = lane & 3;
        uint4 b;
        b.x = f2tf32(Wt[kh * 8 + tc][ntp * 16 + g2]);
        b.y = f2tf32(Wt[kh * 8 + tc + 4][ntp * 16 + g2]);
        b.z = f2tf32(Wt[kh * 8 + tc][ntp * 16 + 8 + g2]);
        b.w = f2tf32(Wt[kh * 8 + tc + 4][ntp * 16 + 8 + g2]);
        g_Bfrag[(size_t)(blockIdx.x * 8 + w) * 32 + lane] = b;
    }
}

// ---------------------------------------------------------------------------
// Kernel C (main): D[128,64] += P[128,1024] @ Wh[1024,64] via mma.tf32.
// R14 structure (best measured); raw fp32 bits into mma.tf32 (no CVT).
// Per-warp adj cp.async rings (PIPE=4), no CTA barriers in the loop.
// ---------------------------------------------------------------------------
#define SADJW(w, b, r, c) \
    s_adj[(w) * (PIPE * WBUF) + (b) * WBUF + (r) * WSTR + (c)]

__global__ __launch_bounds__(256, 2) void gat_mma_kernel(const int* __restrict__ adj) {
    __shared__ int    s_adj[8 * PIPE * WBUF];  // 72 KB
    __shared__ float2 s_E[1024];               // 8 KB
    __shared__ float  sA1[NTILE], sA2[NTILE];

    const int tid = threadIdx.x, lane = tid & 31, warp = tid >> 5;
    const int g = lane >> 2, tc = lane & 3;
    const int it = blockIdx.x >> 3, js = blockIdx.x & 7;
    const int row0 = it * NTILE, jbase = js * (NST * JSTEP);

    const int strow = lane >> 1, stcol = (lane & 1) * 16;
    const int* gsrc = adj + (size_t)(row0 + warp * 16 + strow) * N + jbase + stcol;
    const uint32_t sw_lane =
        (uint32_t)__cvta_generic_to_shared(&SADJW(warp, 0, strow, stcol));

#pragma unroll
    for (int t = 0; t < PIPE - 1; t++) {
        const uint32_t sd = sw_lane + (uint32_t)(t * WBUF) * 4u;
#pragma unroll
        for (int q = 0; q < 4; q++)
            CP_ASYNC16(sd + q * 16, gsrc + t * JSTEP + q * 4);
        CP_COMMIT();
    }

    for (int k = tid; k < 1024; k += 256)
        s_E[k] = make_float2(g_E1[jbase + k], g_E2[jbase + k]);
    if (tid < NTILE) {
        const float fs = g_fsrc[row0 + tid];
        float M = fs + dec_f(g_gmax_enc);
        M = M > 0.f ? M : 0.2f * M;  // lrelu monotone -> valid row upper bound
        sA1[tid] = __expf(fs - M);
        sA2[tid] = __expf(0.2f * fs - M);
    }
    __syncthreads();

    const int lr0 = warp * 16 + g, lr1 = lr0 + 8;
    const int gr0 = row0 + lr0, gr1 = row0 + lr1;
    float2 A0f = make_float2(sA1[lr0], sA2[lr0]);
    float2 A1f = make_float2(sA1[lr1], sA2[lr1]);
    const unsigned long long Ap0 = *(unsigned long long*)&A0f;
    const unsigned long long Ap1 = *(unsigned long long*)&A1f;

    float d[8][4];
#pragma unroll
    for (int nt = 0; nt < 8; nt++)
#pragma unroll
        for (int q = 0; q < 4; q++) d[nt][q] = 0.f;
    float l0 = 0.f, l1 = 0.f;

    for (int s = 0; s < NST; s++) {
        const int buf = s % PIPE;
        CP_WAIT(PIPE - 2);  // tile s arrived (later groups may be in flight)
        __syncwarp();

        if (s + PIPE - 1 < NST) {
            const int t = s + PIPE - 1;
            const uint32_t sd = sw_lane + (uint32_t)((t % PIPE) * WBUF) * 4u;
#pragma unroll
            for (int q = 0; q < 4; q++)
                CP_ASYNC16(sd + q * 16, gsrc + t * JSTEP + q * 4);
        }
        CP_COMMIT();

        // ---- p for 2 rows x 8 cols {tc + 4cq}: packed f32x2 mul + FMNMX ----
        const int jl = s * JSTEP;
        float p0[8], p1[8];
#pragma unroll
        for (int cq = 0; cq < 8; cq++) {
            const int c = tc + cq * 4;
            const unsigned long long e =
                *(const unsigned long long*)&s_E[jl + c];
            unsigned long long t0, t1;
            MUL_F32X2(t0, Ap0, e);  // {A1*E1, A2*E2}
            MUL_F32X2(t1, Ap1, e);
            float v0 = fmaxf(__uint_as_float((unsigned)t0),
                             __uint_as_float((unsigned)(t0 >> 32)));
            float v1 = fmaxf(__uint_as_float((unsigned)t1),
                             __uint_as_float((unsigned)(t1 >> 32)));
            p0[cq] = SADJW(warp, buf, g, c) ? v0 : 0.f;
            p1[cq] = SADJW(warp, buf, g + 8, c) ? v1 : 0.f;
            l0 += p0[cq];
            l1 += p1[cq];
        }

        // ---- 4 K-groups of 8 j: MMAs (B fragments from L2, raw fp32 A) ----
        const uint4* fp =
            &g_Bfrag[(size_t)((js * 64 + 2 * s) * 2) * 4 * 32 + lane];
#pragma unroll
        for (int kk = 0; kk < 4; kk++) {
            const uint4* bp = fp + (size_t)kk * 128;
            const uint32_t a0 = __float_as_uint(p0[kk * 2]);
            const uint32_t a1 = __float_as_uint(p1[kk * 2]);
            const uint32_t a2 = __float_as_uint(p0[kk * 2 + 1]);
            const uint32_t a3 = __float_as_uint(p1[kk * 2 + 1]);
            const uint4 B0 = bp[0];
            const uint4 B1 = bp[32];
            const uint4 B2 = bp[64];
            const uint4 B3 = bp[96];
            mma_tf32(d[0], a0, a1, a2, a3, B0.x, B0.y);
            mma_tf32(d[1], a0, a1, a2, a3, B0.z, B0.w);
            mma_tf32(d[2], a0, a1, a2, a3, B1.x, B1.y);
            mma_tf32(d[3], a0, a1, a2, a3, B1.z, B1.w);
            mma_tf32(d[4], a0, a1, a2, a3, B2.x, B2.y);
            mma_tf32(d[5], a0, a1, a2, a3, B2.z, B2.w);
            mma_tf32(d[6], a0, a1, a2, a3, B3.x, B3.y);
            mma_tf32(d[7], a0, a1, a2, a3, B3.z, B3.w);
        }
    }

    // write D partials
#pragma unroll
    for (int nt = 0; nt < 8; nt++) {
        const int f = nt * 8 + 2 * tc;
        *(float2*)&g_Dpart[js][(size_t)gr0 * FOUT + f] =
            make_float2(d[nt][0], d[nt][1]);
        *(float2*)&g_Dpart[js][(size_t)gr1 * FOUT + f] =
            make_float2(d[nt][2], d[nt][3]);
    }
    // row sums: reduce over tc (lanes g*4..g*4+3)
    l0 += __shfl_xor_sync(0xffffffffu, l0, 1);
    l0 += __shfl_xor_sync(0xffffffffu, l0, 2);
    l1 += __shfl_xor_sync(0xffffffffu, l1, 1);
    l1 += __shfl_xor_sync(0xffffffffu, l1, 2);
    if (tc == 0) {
        g_lpart[js][gr0] = l0;
        g_lpart[js][gr1] = l1;
    }
}

// ---------------------------------------------------------------------------
// Kernel E: combine partials, divide, ELU.
// ---------------------------------------------------------------------------
__global__ __launch_bounds__(256) void fixup_kernel(float* __restrict__ out) {
    const int idx = blockIdx.x * 256 + threadIdx.x;
    const int i = idx >> 4;
    const int f4 = (idx & 15) * 4;
    float4 acc = make_float4(0.f, 0.f, 0.f, 0.f);
    float l = 0.f;
#pragma unroll
    for (int js = 0; js < NSPLIT; js++) {
        const float4 dv = *(const float4*)&g_Dpart[js][(size_t)i * FOUT + f4];
        acc.x += dv.x; acc.y += dv.y; acc.z += dv.z; acc.w += dv.w;
        l += g_lpart[js][i];
    }
    const float inv = 1.f / l;
    float o0 = acc.x * inv, o1 = acc.y * inv, o2 = acc.z * inv, o3 = acc.w * inv;
    o0 = o0 > 0.f ? o0 : expm1f(o0);
    o1 = o1 > 0.f ? o1 : expm1f(o1);
    o2 = o2 > 0.f ? o2 : expm1f(o2);
    o3 = o3 > 0.f ? o3 : expm1f(o3);
    *(float4*)&out[(size_t)i * FOUT + f4] = make_float4(o0, o1, o2, o3);
}

// ---------------------------------------------------------------------------
extern "C" void kernel_launch(void* const* d_in, const int* in_sizes, int n_in,
                              void* d_out, int out_size) {
    const float* h = (const float*)d_in[0];
    const int* adj = (const int*)d_in[1];
    const float* W = (const float*)d_in[2];
    const float* a = (const float*)d_in[3];
    float* out = (float*)d_out;

    void* gmax_ptr = nullptr;
    cudaGetSymbolAddress(&gmax_ptr, g_gmax_enc);
    cudaMemsetAsync(gmax_ptr, 0, sizeof(unsigned));

    wh_fused_kernel<<<N / 16, 256>>>(h, W, a);
    gat_mma_kernel<<<(N / NTILE) * NSPLIT, 256>>>(adj);
    fixup_kernel<<<N * 16 / 256, 256>>>(out);
}